// round 10
// baseline (speedup 1.0000x reference)
#include <cuda_runtime.h>
#include <cuda_bf16.h>
#include <cstdint>

// ---------------- scratch (device globals: no allocation allowed) ----------
#define MAX_NODES 100000
#define MAX_EDGES 1600000
__device__ __align__(16) float g_mean[(size_t)MAX_NODES * 128];
__device__ int g_cnt[MAX_NODES];
__device__ int g_start[MAX_NODES];
__device__ int g_cursor[MAX_NODES];
__device__ int g_eid[MAX_EDGES];
// Transposed, k-chunked bf16 hi/lo weights:
// per layer: [kc][split][n][32] ; L1 @0 (131072), L2 @131072, L3 @262144
__device__ __align__(16) __nv_bfloat16 g_Wt[327680];

// ---------------- helpers ---------------------------------------------------
__device__ __forceinline__ uint32_t smem_u32(const void* p) {
    uint32_t a;
    asm("{ .reg .u64 t; cvta.to.shared.u64 t, %1; cvt.u32.u64 %0, t; }"
        : "=r"(a) : "l"(p));
    return a;
}
__device__ __forceinline__ void cp_async16(uint32_t saddr, const void* g) {
    asm volatile("cp.async.cg.shared.global [%0], [%1], 16;" :: "r"(saddr), "l"(g));
}
__device__ __forceinline__ void ldm_x4(uint32_t* r, uint32_t addr) {
    asm volatile("ldmatrix.sync.aligned.m8n8.x4.shared.b16 {%0,%1,%2,%3}, [%4];"
        : "=r"(r[0]), "=r"(r[1]), "=r"(r[2]), "=r"(r[3]) : "r"(addr));
}
__device__ __forceinline__ void mma_bf16(float* c, const uint32_t* a,
                                         uint32_t b0, uint32_t b1) {
    asm volatile("mma.sync.aligned.m16n8k16.row.col.f32.bf16.bf16.f32 "
        "{%0,%1,%2,%3}, {%4,%5,%6,%7}, {%8,%9}, {%0,%1,%2,%3};"
        : "+f"(c[0]), "+f"(c[1]), "+f"(c[2]), "+f"(c[3])
        : "r"(a[0]), "r"(a[1]), "r"(a[2]), "r"(a[3]), "r"(b0), "r"(b1));
}
__device__ __forceinline__ uint32_t pack_bf(__nv_bfloat16 a, __nv_bfloat16 b) {
    return (uint32_t)__bfloat16_as_ushort(a) | ((uint32_t)__bfloat16_as_ushort(b) << 16);
}

// smem layout (bytes)
constexpr int TPB      = 512;                 // 16 warps (4/SMSP)
constexpr int AS       = 264;                 // A row stride (elements)
constexpr int A_HI_OFF = 0;                   // 128*264*2 = 67584
constexpr int A_LO_OFF = 67584;
constexpr int B_OFF    = 135168;
constexpr int BUFSZ    = 40960;               // one B buffer (OUT=256 worst case)
constexpr int SMEM_TOTAL = B_OFF + 2 * BUFSZ; // 217088

__device__ __forceinline__ void store_split(char* smem, int row, int col,
                                            float v0, float v1) {
    __nv_bfloat16 h0 = __float2bfloat16(v0), h1 = __float2bfloat16(v1);
    __nv_bfloat16 l0 = __float2bfloat16(v0 - __bfloat162float(h0));
    __nv_bfloat16 l1 = __float2bfloat16(v1 - __bfloat162float(h1));
    uint32_t off = (uint32_t)(row * AS + col) * 2;
    *(uint32_t*)(smem + A_HI_OFF + off) = pack_bf(h0, h1);
    *(uint32_t*)(smem + A_LO_OFF + off) = pack_bf(l0, l1);
}

// ---------------- scatter replacement: counting sort + gather ---------------
__global__ void zero_cnt_kernel(int n_nodes) {
    int i = blockIdx.x * blockDim.x + threadIdx.x;
    if (i < n_nodes) g_cnt[i] = 0;
}

__global__ void hist_kernel(const int* __restrict__ col, int n_edges) {
    int e = blockIdx.x * blockDim.x + threadIdx.x;
    if (e < n_edges) atomicAdd(&g_cnt[__ldg(col + e)], 1);
}

// single-block exclusive scan of g_cnt -> g_start; also zero g_cursor
__global__ void scan_kernel(int n_nodes) {
    __shared__ int ssum[1024];
    int t = threadIdx.x;
    int per = (n_nodes + 1023) / 1024;
    int lo = t * per, hi = min(lo + per, n_nodes);
    int s = 0;
    for (int i = lo; i < hi; ++i) s += g_cnt[i];
    ssum[t] = s;
    __syncthreads();
    for (int off = 1; off < 1024; off <<= 1) {
        int v = (t >= off) ? ssum[t - off] : 0;
        __syncthreads();
        ssum[t] += v;
        __syncthreads();
    }
    int run = (t > 0) ? ssum[t - 1] : 0;      // exclusive prefix
    for (int i = lo; i < hi; ++i) { g_start[i] = run; run += g_cnt[i]; }
    for (int i = t; i < n_nodes; i += 1024) g_cursor[i] = 0;
}

__global__ void reorder_kernel(const int* __restrict__ col, int n_edges) {
    int e = blockIdx.x * blockDim.x + threadIdx.x;
    if (e >= n_edges) return;
    int c = __ldg(col + e);
    int pos = atomicAdd(&g_cursor[c], 1);
    g_eid[g_start[c] + pos] = e;
}

// one warp per node: sum its edge rows (coalesced 512B each), write the mean
__global__ void gather_kernel(const float* __restrict__ edge_attr, int n_nodes) {
    int w = (blockIdx.x * blockDim.x + threadIdx.x) >> 5;
    int lane = threadIdx.x & 31;
    if (w >= n_nodes) return;
    int start = g_start[w], deg = g_cnt[w];
    float4 acc = make_float4(0.f, 0.f, 0.f, 0.f);
    int j = 0;
    for (; j + 2 <= deg; j += 2) {            // 2 edges in flight
        int e0 = __ldg(g_eid + start + j);
        int e1 = __ldg(g_eid + start + j + 1);
        float4 v0 = __ldg((const float4*)edge_attr + (size_t)e0 * 32 + lane);
        float4 v1 = __ldg((const float4*)edge_attr + (size_t)e1 * 32 + lane);
        acc.x += v0.x + v1.x; acc.y += v0.y + v1.y;
        acc.z += v0.z + v1.z; acc.w += v0.w + v1.w;
    }
    if (j < deg) {
        int e0 = __ldg(g_eid + start + j);
        float4 v0 = __ldg((const float4*)edge_attr + (size_t)e0 * 32 + lane);
        acc.x += v0.x; acc.y += v0.y; acc.z += v0.z; acc.w += v0.w;
    }
    float inv = deg > 0 ? 1.f / (float)deg : 0.f;
    acc.x *= inv; acc.y *= inv; acc.z *= inv; acc.w *= inv;
    ((float4*)g_mean)[(size_t)w * 32 + lane] = acc;
}

// ---------------- kernel: prep weights -> g_Wt (coalesced via smem tile) ---
__global__ void prep_kernel(const float* __restrict__ W1,
                            const float* __restrict__ W2,
                            const float* __restrict__ W3) {
    __shared__ float tile[32][65];
    int b = blockIdx.x;
    const float* W; int base, OUT, t;
    if (b < 32)      { W = W1; base = 0;      OUT = 256; t = b; }
    else if (b < 64) { W = W2; base = 131072; OUT = 256; t = b - 32; }
    else             { W = W3; base = 262144; OUT = 128; t = b - 64; }
    int nbt = OUT / 64;
    int kc = t / nbt, nb = t % nbt;
    int tid = threadIdx.x;
    #pragma unroll
    for (int i = 0; i < 8; ++i) {
        int idx = tid + i * 256;
        int kr = idx >> 6, nc = idx & 63;
        tile[kr][nc] = __ldg(W + (size_t)(kc * 32 + kr) * OUT + nb * 64 + nc);
    }
    __syncthreads();
    int nn = tid >> 2, kq = tid & 3;
    uint4 vh, vl;
    uint32_t* ph = (uint32_t*)&vh;
    uint32_t* pl = (uint32_t*)&vl;
    #pragma unroll
    for (int j = 0; j < 4; ++j) {
        float w0 = tile[kq * 8 + 2 * j][nn];
        float w1 = tile[kq * 8 + 2 * j + 1][nn];
        __nv_bfloat16 h0 = __float2bfloat16(w0), h1 = __float2bfloat16(w1);
        __nv_bfloat16 l0 = __float2bfloat16(w0 - __bfloat162float(h0));
        __nv_bfloat16 l1 = __float2bfloat16(w1 - __bfloat162float(h1));
        ph[j] = pack_bf(h0, h1);
        pl[j] = pack_bf(l0, l1);
    }
    size_t o_hi = (size_t)base + ((size_t)(kc * 2 + 0) * OUT + nb * 64 + nn) * 32 + kq * 8;
    size_t o_lo = (size_t)base + ((size_t)(kc * 2 + 1) * OUT + nb * 64 + nn) * 32 + kq * 8;
    *(uint4*)(g_Wt + o_hi) = vh;
    *(uint4*)(g_Wt + o_lo) = vl;
}

// ---------------- B chunk loader (linear cp.async into padded rows) --------
template<int OUT>
__device__ __forceinline__ void load_chunk(uint32_t bdst, const __nv_bfloat16* gsrc) {
    constexpr int UNITS = OUT * 8;
    constexpr int SSTR  = OUT * 80;
    #pragma unroll
    for (int u = threadIdx.x; u < UNITS; u += TPB) {
        int s = u / (UNITS / 2);
        int v = u % (UNITS / 2);
        int nn = v >> 2, part = v & 3;
        uint32_t dst = bdst + s * SSTR + nn * 80 + part * 16;
        cp_async16(dst, (const char*)gsrc + (size_t)u * 16);
    }
    asm volatile("cp.async.commit_group;");
}

// ---------------- one MLP layer on HMMA (R9 structure, unchanged) ----------
template<int IN, int OUT, int OUT_NEXT, bool LAST>
__device__ __forceinline__ void run_layer(char* smem, uint32_t sm_base,
                                          const __nv_bfloat16* gW,
                                          const __nv_bfloat16* gW_next,
                                          const float* __restrict__ bias,
                                          float* __restrict__ out_g,
                                          int nbase, int n)
{
    const int lane = threadIdx.x & 31, wid = threadIdx.x >> 5;
    const int wm = wid >> 2, wn = wid & 3;
    constexpr int NT   = OUT / 32;
    constexpr int T    = IN / 32;
    constexpr int SSTR = OUT * 80;

    const int arow = wm * 32 + (lane & 15);
    const int acol = (lane >> 4) * 8;
    const int b_noff = ((lane >> 4) & 1) * 8 + (lane & 7);
    const int b_kby  = ((lane >> 3) & 1) * 16;

    float acc[2][NT][4];
    #pragma unroll
    for (int mt = 0; mt < 2; ++mt)
        #pragma unroll
        for (int nt = 0; nt < NT; ++nt)
            #pragma unroll
            for (int c = 0; c < 4; ++c) acc[mt][nt][c] = 0.f;

    for (int kc = 0; kc < T; ++kc) {
        int buf = kc & 1;
        if (LAST && kc == T - 1) asm volatile("cp.async.wait_group 0;");
        else                     asm volatile("cp.async.wait_group 1;");
        __syncthreads();

        const uint32_t bbase = sm_base + (uint32_t)(B_OFF + buf * BUFSZ)
                             + (uint32_t)((wn * (NT * 8) + b_noff) * 80 + b_kby);
        #pragma unroll
        for (int ks = 0; ks < 2; ++ks) {
            const int k0 = kc * 32 + ks * 16;
            uint32_t ahi[2][4], alo[2][4];
            #pragma unroll
            for (int mt = 0; mt < 2; ++mt) {
                uint32_t aaddr = sm_base +
                    (uint32_t)(((arow + mt * 16) * AS + k0 + acol) * 2);
                ldm_x4(ahi[mt], aaddr + A_HI_OFF);
                ldm_x4(alo[mt], aaddr + A_LO_OFF);
            }
            uint32_t bh[2][4], bl[2][4];
            {
                uint32_t ba = bbase + (uint32_t)(ks * 32);
                ldm_x4(bh[0], ba);
                ldm_x4(bl[0], ba + SSTR);
            }
            #pragma unroll
            for (int np = 0; np < NT / 2; ++np) {
                const int cur = np & 1, nxt = cur ^ 1;
                if (np + 1 < NT / 2) {
                    uint32_t ba = bbase + (uint32_t)((np + 1) * 16 * 80 + ks * 32);
                    ldm_x4(bh[nxt], ba);
                    ldm_x4(bl[nxt], ba + SSTR);
                }
                #pragma unroll
                for (int q = 0; q < 2; ++q)
                    #pragma unroll
                    for (int mt = 0; mt < 2; ++mt)
                        mma_bf16(acc[mt][np * 2 + q], ahi[mt],
                                 bh[cur][2 * q], bh[cur][2 * q + 1]);
                #pragma unroll
                for (int q = 0; q < 2; ++q)
                    #pragma unroll
                    for (int mt = 0; mt < 2; ++mt)
                        mma_bf16(acc[mt][np * 2 + q], alo[mt],
                                 bh[cur][2 * q], bh[cur][2 * q + 1]);
                #pragma unroll
                for (int q = 0; q < 2; ++q)
                    #pragma unroll
                    for (int mt = 0; mt < 2; ++mt)
                        mma_bf16(acc[mt][np * 2 + q], ahi[mt],
                                 bl[cur][2 * q], bl[cur][2 * q + 1]);
            }
        }
        __syncthreads();

        if (kc + 2 < T) {
            load_chunk<OUT>(sm_base + B_OFF + buf * BUFSZ,
                            gW + (size_t)(kc + 2) * 2 * OUT * 32);
        } else if (!LAST) {
            int nxt = kc + 2 - T;
            load_chunk<OUT_NEXT>(sm_base + B_OFF + buf * BUFSZ,
                                 gW_next + (size_t)nxt * 2 * OUT_NEXT * 32);
        }
    }

    float2 bv[NT];
    #pragma unroll
    for (int nt = 0; nt < NT; ++nt)
        bv[nt] = __ldg((const float2*)(bias + wn * (NT * 8) + nt * 8 + (lane & 3) * 2));

    #pragma unroll
    for (int mt = 0; mt < 2; ++mt) {
        int row0 = wm * 32 + mt * 16 + (lane >> 2);
        #pragma unroll
        for (int nt = 0; nt < NT; ++nt) {
            int col = wn * (NT * 8) + nt * 8 + (lane & 3) * 2;
            float v0 = acc[mt][nt][0] + bv[nt].x, v1 = acc[mt][nt][1] + bv[nt].y;
            float v2 = acc[mt][nt][2] + bv[nt].x, v3 = acc[mt][nt][3] + bv[nt].y;
            if (LAST) {
                int n0 = nbase + row0, n1 = n0 + 8;
                if (n0 < n) {
                    float2 t = {v0, v1};
                    *(float2*)(out_g + (size_t)n0 * OUT + col) = t;
                }
                if (n1 < n) {
                    float2 t = {v2, v3};
                    *(float2*)(out_g + (size_t)n1 * OUT + col) = t;
                }
            } else {
                store_split(smem, row0,     col, fmaxf(v0, 0.f), fmaxf(v1, 0.f));
                store_split(smem, row0 + 8, col, fmaxf(v2, 0.f), fmaxf(v3, 0.f));
            }
        }
    }
    if (!LAST) __syncthreads();
}

// ---------------- kernel: HMMA MLP ------------------------------------------
__global__ void __launch_bounds__(TPB, 1)
mlp_mma_kernel(const float* __restrict__ x,
               const float* __restrict__ b1, const float* __restrict__ b2,
               const float* __restrict__ b3,
               float* __restrict__ out, int n)
{
    extern __shared__ char smem[];
    const uint32_t sm_base = smem_u32(smem);
    const int tid = threadIdx.x;
    const int nbase = blockIdx.x * 128;

    load_chunk<256>(sm_base + B_OFF,         g_Wt);
    load_chunk<256>(sm_base + B_OFF + BUFSZ, g_Wt + 2 * 256 * 32);

    // Build A = concat(x, precomputed mean) as bf16 hi/lo, padded rows.
    {
        int m = tid >> 2, q = tid & 3;
        int node = nbase + m;
        bool valid = node < n;
        const float4* src = (q < 2)
            ? (const float4*)x      + (size_t)node * 32 + q * 16
            : (const float4*)g_mean + (size_t)node * 32 + (q - 2) * 16;
        #pragma unroll 4
        for (int f = 0; f < 16; ++f) {
            float4 v = make_float4(0.f, 0.f, 0.f, 0.f);
            if (valid) v = __ldg(src + f);
            int col = q * 64 + f * 4;
            store_split(smem, m, col,     v.x, v.y);
            store_split(smem, m, col + 2, v.z, v.w);
        }
    }
    __syncthreads();

    run_layer<256, 256, 256, false>(smem, sm_base, g_Wt,          g_Wt + 131072,
                                    b1, nullptr, nbase, n);
    run_layer<256, 256, 128, false>(smem, sm_base, g_Wt + 131072, g_Wt + 262144,
                                    b2, nullptr, nbase, n);
    run_layer<256, 128, 128, true >(smem, sm_base, g_Wt + 262144, nullptr,
                                    b3, out, nbase, n);
}

// ---------------- launcher --------------------------------------------------
extern "C" void kernel_launch(void* const* d_in, const int* in_sizes, int n_in,
                              void* d_out, int out_size)
{
    const float* x          = (const float*)d_in[0];
    const int*   edge_index = (const int*)  d_in[1];
    const float* edge_attr  = (const float*)d_in[2];
    const float* W1 = (const float*)d_in[3];
    const float* b1 = (const float*)d_in[4];
    const float* W2 = (const float*)d_in[5];
    const float* b2 = (const float*)d_in[6];
    const float* W3 = (const float*)d_in[7];
    const float* b3 = (const float*)d_in[8];
    float* out = (float*)d_out;

    int n_nodes = in_sizes[0] / 128;
    int n_edges = in_sizes[1] / 2;
    const int* col = edge_index + n_edges;

    cudaFuncSetAttribute(mlp_mma_kernel,
                         cudaFuncAttributeMaxDynamicSharedMemorySize, SMEM_TOTAL);

    // counting-sort + gather mean pipeline
    zero_cnt_kernel<<<(n_nodes + 255) / 256, 256>>>(n_nodes);
    hist_kernel<<<(n_edges + 255) / 256, 256>>>(col, n_edges);
    scan_kernel<<<1, 1024>>>(n_nodes);
    reorder_kernel<<<(n_edges + 255) / 256, 256>>>(col, n_edges);
    prep_kernel<<<80, 256>>>(W1, W2, W3);
    {
        int warps = n_nodes;
        int blocks = (warps * 32 + 255) / 256;
        gather_kernel<<<blocks, 256>>>(edge_attr, n_nodes);
    }
    // HMMA MLP
    {
        int blocks = (n_nodes + 127) / 128;
        mlp_mma_kernel<<<blocks, TPB, SMEM_TOTAL>>>(x, b1, b2, b3, out, n_nodes);
    }
}

// round 11
// speedup vs baseline: 1.0106x; 1.0106x over previous
#include <cuda_runtime.h>
#include <cuda_bf16.h>
#include <cstdint>

// ---------------- scratch (device globals: no allocation allowed) ----------
#define MAX_NODES 100000
__device__ __align__(16) float g_sums[(size_t)MAX_NODES * 128];
__device__ float g_counts[MAX_NODES];
// Transposed, k-chunked bf16 hi/lo weights:
// per layer: [kc][split][n][32] ; L1 @0 (131072), L2 @131072, L3 @262144
__device__ __align__(16) __nv_bfloat16 g_Wt[327680];

// ---------------- helpers ---------------------------------------------------
__device__ __forceinline__ uint32_t smem_u32(const void* p) {
    uint32_t a;
    asm("{ .reg .u64 t; cvta.to.shared.u64 t, %1; cvt.u32.u64 %0, t; }"
        : "=r"(a) : "l"(p));
    return a;
}
__device__ __forceinline__ void cp_async16(uint32_t saddr, const void* g) {
    asm volatile("cp.async.cg.shared.global [%0], [%1], 16;" :: "r"(saddr), "l"(g));
}
__device__ __forceinline__ void ldm_x4(uint32_t* r, uint32_t addr) {
    asm volatile("ldmatrix.sync.aligned.m8n8.x4.shared.b16 {%0,%1,%2,%3}, [%4];"
        : "=r"(r[0]), "=r"(r[1]), "=r"(r[2]), "=r"(r[3]) : "r"(addr));
}
__device__ __forceinline__ void mma_bf16(float* c, const uint32_t* a,
                                         uint32_t b0, uint32_t b1) {
    asm volatile("mma.sync.aligned.m16n8k16.row.col.f32.bf16.bf16.f32 "
        "{%0,%1,%2,%3}, {%4,%5,%6,%7}, {%8,%9}, {%0,%1,%2,%3};"
        : "+f"(c[0]), "+f"(c[1]), "+f"(c[2]), "+f"(c[3])
        : "r"(a[0]), "r"(a[1]), "r"(a[2]), "r"(a[3]), "r"(b0), "r"(b1));
}
__device__ __forceinline__ uint32_t pack_bf(__nv_bfloat16 a, __nv_bfloat16 b) {
    return (uint32_t)__bfloat16_as_ushort(a) | ((uint32_t)__bfloat16_as_ushort(b) << 16);
}

// smem layout (bytes)
constexpr int TPB      = 512;                 // 16 warps (4/SMSP)
constexpr int AS       = 264;                 // A row stride (elements)
constexpr int A_HI_OFF = 0;                   // 128*264*2 = 67584
constexpr int A_LO_OFF = 67584;
constexpr int B_OFF    = 135168;
constexpr int BUFSZ    = 40960;               // one B buffer (OUT=256 worst case)
constexpr int SMEM_TOTAL = B_OFF + 2 * BUFSZ; // 217088

__device__ __forceinline__ void store_split(char* smem, int row, int col,
                                            float v0, float v1) {
    __nv_bfloat16 h0 = __float2bfloat16(v0), h1 = __float2bfloat16(v1);
    __nv_bfloat16 l0 = __float2bfloat16(v0 - __bfloat162float(h0));
    __nv_bfloat16 l1 = __float2bfloat16(v1 - __bfloat162float(h1));
    uint32_t off = (uint32_t)(row * AS + col) * 2;
    *(uint32_t*)(smem + A_HI_OFF + off) = pack_bf(h0, h1);
    *(uint32_t*)(smem + A_LO_OFF + off) = pack_bf(l0, l1);
}

// ---------------- kernel 1: zero the scatter accumulators ------------------
__global__ void zero_kernel(int n_nodes) {
    int i = blockIdx.x * blockDim.x + threadIdx.x;
    int n4 = n_nodes * 32;
    if (i < n4) ((float4*)g_sums)[i] = make_float4(0.f, 0.f, 0.f, 0.f);
    if (i < n_nodes) g_counts[i] = 0.f;
}

// ---------------- kernel 2: scatter via cp.reduce.async.bulk ---------------
// One warp per edge: stage the 512B edge row in smem (cp.async), then a
// single 512B bulk-reduce (add.f32) to the destination node row. 1.6M bulk
// ops replace 51.2M per-lane RED.128s on the SM side; L2-side bytes equal.
__global__ void __launch_bounds__(256)
scatter_kernel(const float* __restrict__ edge_attr,
               const int*   __restrict__ col,
               int n_edges) {
    __shared__ __align__(512) char srow[8 * 512];   // 8 warps x 512B
    int t = blockIdx.x * blockDim.x + threadIdx.x;
    int e = t >> 5;
    int lane = t & 31;
    int wloc = (threadIdx.x >> 5);
    if (e >= n_edges) return;
    int c = __ldg(col + e);

    uint32_t sdst = smem_u32(srow) + wloc * 512 + lane * 16;
    cp_async16(sdst, edge_attr + (size_t)e * 128 + lane * 4);
    asm volatile("cp.async.commit_group;");
    asm volatile("cp.async.wait_group 0;");
    __syncwarp();

    if (lane == 0) {
        atomicAdd(g_counts + c, 1.0f);
        asm volatile("fence.proxy.async.shared::cta;" ::: "memory");
        float* gdst = g_sums + (size_t)c * 128;
        uint32_t ssrc = smem_u32(srow) + wloc * 512;
        asm volatile(
            "cp.reduce.async.bulk.global.shared::cta.bulk_group.add.f32 "
            "[%0], [%1], 512;"
            :: "l"(gdst), "r"(ssrc) : "memory");
        asm volatile("cp.async.bulk.commit_group;");
        asm volatile("cp.async.bulk.wait_group 0;" ::: "memory");
    }
}

// ---------------- kernel: prep weights -> g_Wt (coalesced via smem tile) ---
__global__ void prep_kernel(const float* __restrict__ W1,
                            const float* __restrict__ W2,
                            const float* __restrict__ W3) {
    __shared__ float tile[32][65];
    int b = blockIdx.x;
    const float* W; int base, OUT, t;
    if (b < 32)      { W = W1; base = 0;      OUT = 256; t = b; }
    else if (b < 64) { W = W2; base = 131072; OUT = 256; t = b - 32; }
    else             { W = W3; base = 262144; OUT = 128; t = b - 64; }
    int nbt = OUT / 64;
    int kc = t / nbt, nb = t % nbt;
    int tid = threadIdx.x;
    #pragma unroll
    for (int i = 0; i < 8; ++i) {
        int idx = tid + i * 256;
        int kr = idx >> 6, nc = idx & 63;
        tile[kr][nc] = __ldg(W + (size_t)(kc * 32 + kr) * OUT + nb * 64 + nc);
    }
    __syncthreads();
    int nn = tid >> 2, kq = tid & 3;
    uint4 vh, vl;
    uint32_t* ph = (uint32_t*)&vh;
    uint32_t* pl = (uint32_t*)&vl;
    #pragma unroll
    for (int j = 0; j < 4; ++j) {
        float w0 = tile[kq * 8 + 2 * j][nn];
        float w1 = tile[kq * 8 + 2 * j + 1][nn];
        __nv_bfloat16 h0 = __float2bfloat16(w0), h1 = __float2bfloat16(w1);
        __nv_bfloat16 l0 = __float2bfloat16(w0 - __bfloat162float(h0));
        __nv_bfloat16 l1 = __float2bfloat16(w1 - __bfloat162float(h1));
        ph[j] = pack_bf(h0, h1);
        pl[j] = pack_bf(l0, l1);
    }
    size_t o_hi = (size_t)base + ((size_t)(kc * 2 + 0) * OUT + nb * 64 + nn) * 32 + kq * 8;
    size_t o_lo = (size_t)base + ((size_t)(kc * 2 + 1) * OUT + nb * 64 + nn) * 32 + kq * 8;
    *(uint4*)(g_Wt + o_hi) = vh;
    *(uint4*)(g_Wt + o_lo) = vl;
}

// ---------------- B chunk loader (linear cp.async into padded rows) --------
template<int OUT>
__device__ __forceinline__ void load_chunk(uint32_t bdst, const __nv_bfloat16* gsrc) {
    constexpr int UNITS = OUT * 8;
    constexpr int SSTR  = OUT * 80;
    #pragma unroll
    for (int u = threadIdx.x; u < UNITS; u += TPB) {
        int s = u / (UNITS / 2);
        int v = u % (UNITS / 2);
        int nn = v >> 2, part = v & 3;
        uint32_t dst = bdst + s * SSTR + nn * 80 + part * 16;
        cp_async16(dst, (const char*)gsrc + (size_t)u * 16);
    }
    asm volatile("cp.async.commit_group;");
}

// ---------------- one MLP layer on HMMA (R9 structure, unchanged) ----------
template<int IN, int OUT, int OUT_NEXT, bool LAST>
__device__ __forceinline__ void run_layer(char* smem, uint32_t sm_base,
                                          const __nv_bfloat16* gW,
                                          const __nv_bfloat16* gW_next,
                                          const float* __restrict__ bias,
                                          float* __restrict__ out_g,
                                          int nbase, int n)
{
    const int lane = threadIdx.x & 31, wid = threadIdx.x >> 5;
    const int wm = wid >> 2, wn = wid & 3;
    constexpr int NT   = OUT / 32;
    constexpr int T    = IN / 32;
    constexpr int SSTR = OUT * 80;

    const int arow = wm * 32 + (lane & 15);
    const int acol = (lane >> 4) * 8;
    const int b_noff = ((lane >> 4) & 1) * 8 + (lane & 7);
    const int b_kby  = ((lane >> 3) & 1) * 16;

    float acc[2][NT][4];
    #pragma unroll
    for (int mt = 0; mt < 2; ++mt)
        #pragma unroll
        for (int nt = 0; nt < NT; ++nt)
            #pragma unroll
            for (int c = 0; c < 4; ++c) acc[mt][nt][c] = 0.f;

    for (int kc = 0; kc < T; ++kc) {
        int buf = kc & 1;
        if (LAST && kc == T - 1) asm volatile("cp.async.wait_group 0;");
        else                     asm volatile("cp.async.wait_group 1;");
        __syncthreads();

        const uint32_t bbase = sm_base + (uint32_t)(B_OFF + buf * BUFSZ)
                             + (uint32_t)((wn * (NT * 8) + b_noff) * 80 + b_kby);
        #pragma unroll
        for (int ks = 0; ks < 2; ++ks) {
            const int k0 = kc * 32 + ks * 16;
            uint32_t ahi[2][4], alo[2][4];
            #pragma unroll
            for (int mt = 0; mt < 2; ++mt) {
                uint32_t aaddr = sm_base +
                    (uint32_t)(((arow + mt * 16) * AS + k0 + acol) * 2);
                ldm_x4(ahi[mt], aaddr + A_HI_OFF);
                ldm_x4(alo[mt], aaddr + A_LO_OFF);
            }
            uint32_t bh[2][4], bl[2][4];
            {
                uint32_t ba = bbase + (uint32_t)(ks * 32);
                ldm_x4(bh[0], ba);
                ldm_x4(bl[0], ba + SSTR);
            }
            #pragma unroll
            for (int np = 0; np < NT / 2; ++np) {
                const int cur = np & 1, nxt = cur ^ 1;
                if (np + 1 < NT / 2) {
                    uint32_t ba = bbase + (uint32_t)((np + 1) * 16 * 80 + ks * 32);
                    ldm_x4(bh[nxt], ba);
                    ldm_x4(bl[nxt], ba + SSTR);
                }
                #pragma unroll
                for (int q = 0; q < 2; ++q)
                    #pragma unroll
                    for (int mt = 0; mt < 2; ++mt)
                        mma_bf16(acc[mt][np * 2 + q], ahi[mt],
                                 bh[cur][2 * q], bh[cur][2 * q + 1]);
                #pragma unroll
                for (int q = 0; q < 2; ++q)
                    #pragma unroll
                    for (int mt = 0; mt < 2; ++mt)
                        mma_bf16(acc[mt][np * 2 + q], alo[mt],
                                 bh[cur][2 * q], bh[cur][2 * q + 1]);
                #pragma unroll
                for (int q = 0; q < 2; ++q)
                    #pragma unroll
                    for (int mt = 0; mt < 2; ++mt)
                        mma_bf16(acc[mt][np * 2 + q], ahi[mt],
                                 bl[cur][2 * q], bl[cur][2 * q + 1]);
            }
        }
        __syncthreads();

        if (kc + 2 < T) {
            load_chunk<OUT>(sm_base + B_OFF + buf * BUFSZ,
                            gW + (size_t)(kc + 2) * 2 * OUT * 32);
        } else if (!LAST) {
            int nxt = kc + 2 - T;
            load_chunk<OUT_NEXT>(sm_base + B_OFF + buf * BUFSZ,
                                 gW_next + (size_t)nxt * 2 * OUT_NEXT * 32);
        }
    }

    float2 bv[NT];
    #pragma unroll
    for (int nt = 0; nt < NT; ++nt)
        bv[nt] = __ldg((const float2*)(bias + wn * (NT * 8) + nt * 8 + (lane & 3) * 2));

    #pragma unroll
    for (int mt = 0; mt < 2; ++mt) {
        int row0 = wm * 32 + mt * 16 + (lane >> 2);
        #pragma unroll
        for (int nt = 0; nt < NT; ++nt) {
            int col = wn * (NT * 8) + nt * 8 + (lane & 3) * 2;
            float v0 = acc[mt][nt][0] + bv[nt].x, v1 = acc[mt][nt][1] + bv[nt].y;
            float v2 = acc[mt][nt][2] + bv[nt].x, v3 = acc[mt][nt][3] + bv[nt].y;
            if (LAST) {
                int n0 = nbase + row0, n1 = n0 + 8;
                if (n0 < n) {
                    float2 t = {v0, v1};
                    *(float2*)(out_g + (size_t)n0 * OUT + col) = t;
                }
                if (n1 < n) {
                    float2 t = {v2, v3};
                    *(float2*)(out_g + (size_t)n1 * OUT + col) = t;
                }
            } else {
                store_split(smem, row0,     col, fmaxf(v0, 0.f), fmaxf(v1, 0.f));
                store_split(smem, row0 + 8, col, fmaxf(v2, 0.f), fmaxf(v3, 0.f));
            }
        }
    }
    if (!LAST) __syncthreads();
}

// ---------------- kernel 3: HMMA MLP ----------------------------------------
__global__ void __launch_bounds__(TPB, 1)
mlp_mma_kernel(const float* __restrict__ x,
               const float* __restrict__ b1, const float* __restrict__ b2,
               const float* __restrict__ b3,
               float* __restrict__ out, int n)
{
    extern __shared__ char smem[];
    const uint32_t sm_base = smem_u32(smem);
    const int tid = threadIdx.x;
    const int nbase = blockIdx.x * 128;

    load_chunk<256>(sm_base + B_OFF,         g_Wt);
    load_chunk<256>(sm_base + B_OFF + BUFSZ, g_Wt + 2 * 256 * 32);

    // Build A = concat(x, scatter-mean) as bf16 hi/lo, padded rows.
    {
        int m = tid >> 2, q = tid & 3;
        int node = nbase + m;
        bool valid = node < n;
        const float4* src = (q < 2)
            ? (const float4*)x      + (size_t)node * 32 + q * 16
            : (const float4*)g_sums + (size_t)node * 32 + (q - 2) * 16;
        float inv = 1.f;
        if (valid && q >= 2) inv = 1.f / fmaxf(g_counts[node], 1.f);
        #pragma unroll 4
        for (int f = 0; f < 16; ++f) {
            float4 v = make_float4(0.f, 0.f, 0.f, 0.f);
            if (valid) {
                v = __ldg(src + f);
                if (q >= 2) { v.x *= inv; v.y *= inv; v.z *= inv; v.w *= inv; }
            }
            int col = q * 64 + f * 4;
            store_split(smem, m, col,     v.x, v.y);
            store_split(smem, m, col + 2, v.z, v.w);
        }
    }
    __syncthreads();

    run_layer<256, 256, 256, false>(smem, sm_base, g_Wt,          g_Wt + 131072,
                                    b1, nullptr, nbase, n);
    run_layer<256, 256, 128, false>(smem, sm_base, g_Wt + 131072, g_Wt + 262144,
                                    b2, nullptr, nbase, n);
    run_layer<256, 128, 128, true >(smem, sm_base, g_Wt + 262144, nullptr,
                                    b3, out, nbase, n);
}

// ---------------- launcher --------------------------------------------------
extern "C" void kernel_launch(void* const* d_in, const int* in_sizes, int n_in,
                              void* d_out, int out_size)
{
    const float* x          = (const float*)d_in[0];
    const int*   edge_index = (const int*)  d_in[1];
    const float* edge_attr  = (const float*)d_in[2];
    const float* W1 = (const float*)d_in[3];
    const float* b1 = (const float*)d_in[4];
    const float* W2 = (const float*)d_in[5];
    const float* b2 = (const float*)d_in[6];
    const float* W3 = (const float*)d_in[7];
    const float* b3 = (const float*)d_in[8];
    float* out = (float*)d_out;

    int n_nodes = in_sizes[0] / 128;
    int n_edges = in_sizes[1] / 2;
    const int* col = edge_index + n_edges;

    cudaFuncSetAttribute(mlp_mma_kernel,
                         cudaFuncAttributeMaxDynamicSharedMemorySize, SMEM_TOTAL);

    // 1) zero accumulators
    {
        int n4 = n_nodes * 32;
        zero_kernel<<<(n4 + 255) / 256, 256>>>(n_nodes);
    }
    // 2) prep weights (bf16 hi/lo, transposed + k-chunked, coalesced)
    prep_kernel<<<80, 256>>>(W1, W2, W3);
    // 3) scatter-add via bulk reduce (one warp per edge)
    {
        long long total = (long long)n_edges * 32;
        scatter_kernel<<<(int)((total + 255) / 256), 256>>>(edge_attr, col, n_edges);
    }
    // 4) HMMA MLP
    {
        int blocks = (n_nodes + 127) / 128;
        mlp_mma_kernel<<<blocks, TPB, SMEM_TOTAL>>>(x, b1, b2, b3, out, n_nodes);
    }
}

// round 12
// speedup vs baseline: 1.1961x; 1.1836x over previous
#include <cuda_runtime.h>
#include <cuda_bf16.h>
#include <cstdint>

// ---------------- scratch (device globals: no allocation allowed) ----------
#define MAX_NODES 100000
__device__ __align__(16) float g_sums[(size_t)MAX_NODES * 128];
__device__ float g_counts[MAX_NODES];
// Transposed, k-chunked bf16 hi/lo weights:
// per layer: [kc][split][n][32] ; L1 @0 (131072), L2 @131072, L3 @262144
__device__ __align__(16) __nv_bfloat16 g_Wt[327680];

// ---------------- helpers ---------------------------------------------------
__device__ __forceinline__ uint32_t smem_u32(const void* p) {
    uint32_t a;
    asm("{ .reg .u64 t; cvta.to.shared.u64 t, %1; cvt.u32.u64 %0, t; }"
        : "=r"(a) : "l"(p));
    return a;
}
__device__ __forceinline__ void cp_async16(uint32_t saddr, const void* g) {
    asm volatile("cp.async.cg.shared.global [%0], [%1], 16;" :: "r"(saddr), "l"(g));
}
__device__ __forceinline__ void ldm_x4(uint32_t* r, uint32_t addr) {
    asm volatile("ldmatrix.sync.aligned.m8n8.x4.shared.b16 {%0,%1,%2,%3}, [%4];"
        : "=r"(r[0]), "=r"(r[1]), "=r"(r[2]), "=r"(r[3]) : "r"(addr));
}
__device__ __forceinline__ void mma_bf16(float* c, const uint32_t* a,
                                         uint32_t b0, uint32_t b1) {
    asm volatile("mma.sync.aligned.m16n8k16.row.col.f32.bf16.bf16.f32 "
        "{%0,%1,%2,%3}, {%4,%5,%6,%7}, {%8,%9}, {%0,%1,%2,%3};"
        : "+f"(c[0]), "+f"(c[1]), "+f"(c[2]), "+f"(c[3])
        : "r"(a[0]), "r"(a[1]), "r"(a[2]), "r"(a[3]), "r"(b0), "r"(b1));
}
__device__ __forceinline__ uint32_t pack_bf(__nv_bfloat16 a, __nv_bfloat16 b) {
    return (uint32_t)__bfloat16_as_ushort(a) | ((uint32_t)__bfloat16_as_ushort(b) << 16);
}

// smem layout (bytes) — M=64 CTA, 2 CTAs/SM
constexpr int TPB      = 256;                 // 8 warps per CTA
constexpr int MROWS    = 64;                  // nodes per CTA
constexpr int AS       = 264;                 // A row stride (elements)
constexpr int A_HI_OFF = 0;                   // 64*264*2 = 33792
constexpr int A_LO_OFF = 33792;
constexpr int B_OFF    = 67584;
constexpr int BUFSZ    = 20480;               // one B split-tile (OUT=256: 256*80)
constexpr int SMEM_TOTAL = B_OFF + 2 * BUFSZ; // 108544 -> 2 CTAs/SM

__device__ __forceinline__ void store_split(char* smem, int row, int col,
                                            float v0, float v1) {
    __nv_bfloat16 h0 = __float2bfloat16(v0), h1 = __float2bfloat16(v1);
    __nv_bfloat16 l0 = __float2bfloat16(v0 - __bfloat162float(h0));
    __nv_bfloat16 l1 = __float2bfloat16(v1 - __bfloat162float(h1));
    uint32_t off = (uint32_t)(row * AS + col) * 2;
    *(uint32_t*)(smem + A_HI_OFF + off) = pack_bf(h0, h1);
    *(uint32_t*)(smem + A_LO_OFF + off) = pack_bf(l0, l1);
}

// ---------------- kernel 1: zero the scatter accumulators ------------------
__global__ void zero_kernel(int n_nodes) {
    int i = blockIdx.x * blockDim.x + threadIdx.x;
    int n4 = n_nodes * 32;
    if (i < n4) ((float4*)g_sums)[i] = make_float4(0.f, 0.f, 0.f, 0.f);
    if (i < n_nodes) g_counts[i] = 0.f;
}

// ---------------- kernel 2: scatter-add (vector atomics, R9 form) ----------
__global__ void scatter_kernel(const float* __restrict__ edge_attr,
                               const int*   __restrict__ col,
                               int n_edges) {
    int t = blockIdx.x * blockDim.x + threadIdx.x;
    int e = t >> 5;
    int lane = t & 31;
    if (e >= n_edges) return;
    int c = __ldg(col + e);
    float4 v = ((const float4*)edge_attr)[(size_t)e * 32 + lane];
    float* dst = g_sums + (size_t)c * 128 + lane * 4;
    asm volatile("red.global.add.v4.f32 [%0], {%1,%2,%3,%4};"
                 :: "l"(dst), "f"(v.x), "f"(v.y), "f"(v.z), "f"(v.w) : "memory");
    if (lane == 0) atomicAdd(g_counts + c, 1.0f);
}

// ---------------- kernel: prep weights -> g_Wt (coalesced via smem tile) ---
__global__ void prep_kernel(const float* __restrict__ W1,
                            const float* __restrict__ W2,
                            const float* __restrict__ W3) {
    __shared__ float tile[32][65];
    int b = blockIdx.x;
    const float* W; int base, OUT, t;
    if (b < 32)      { W = W1; base = 0;      OUT = 256; t = b; }
    else if (b < 64) { W = W2; base = 131072; OUT = 256; t = b - 32; }
    else             { W = W3; base = 262144; OUT = 128; t = b - 64; }
    int nbt = OUT / 64;
    int kc = t / nbt, nb = t % nbt;
    int tid = threadIdx.x;
    #pragma unroll
    for (int i = 0; i < 8; ++i) {
        int idx = tid + i * 256;
        int kr = idx >> 6, nc = idx & 63;
        tile[kr][nc] = __ldg(W + (size_t)(kc * 32 + kr) * OUT + nb * 64 + nc);
    }
    __syncthreads();
    int nn = tid >> 2, kq = tid & 3;
    uint4 vh, vl;
    uint32_t* ph = (uint32_t*)&vh;
    uint32_t* pl = (uint32_t*)&vl;
    #pragma unroll
    for (int j = 0; j < 4; ++j) {
        float w0 = tile[kq * 8 + 2 * j][nn];
        float w1 = tile[kq * 8 + 2 * j + 1][nn];
        __nv_bfloat16 h0 = __float2bfloat16(w0), h1 = __float2bfloat16(w1);
        __nv_bfloat16 l0 = __float2bfloat16(w0 - __bfloat162float(h0));
        __nv_bfloat16 l1 = __float2bfloat16(w1 - __bfloat162float(h1));
        ph[j] = pack_bf(h0, h1);
        pl[j] = pack_bf(l0, l1);
    }
    size_t o_hi = (size_t)base + ((size_t)(kc * 2 + 0) * OUT + nb * 64 + nn) * 32 + kq * 8;
    size_t o_lo = (size_t)base + ((size_t)(kc * 2 + 1) * OUT + nb * 64 + nn) * 32 + kq * 8;
    *(uint4*)(g_Wt + o_hi) = vh;
    *(uint4*)(g_Wt + o_lo) = vl;
}

// ---------------- B split-tile loader (one split of one kc) ----------------
// tile = OUT rows x 32 k bf16, contiguous in gmem; smem rows 80B (64 data+16 pad)
template<int OUT>
__device__ __forceinline__ void load_tile(uint32_t bdst, const __nv_bfloat16* gsrc) {
    constexpr int UNITS = OUT * 4;            // 16B units
    #pragma unroll
    for (int u = threadIdx.x; u < UNITS; u += TPB) {
        int nn = u >> 2, part = u & 3;
        cp_async16(bdst + nn * 80 + part * 16, (const char*)gsrc + (size_t)u * 16);
    }
    asm volatile("cp.async.commit_group;");
}

// ---------------- one MLP layer on HMMA (M=64, per-split B tiles) ----------
// Warp grid 2(m) x 4(n). Tiles this layer: 16 (8 kc x {hi,lo}), tile t in
// buffer t&1. Entry invariant: tiles 0,1 committed. After computing a tile,
// tile t+2 (or next layer's tile t+2-16) is committed into the freed buffer.
template<int OUT, int OUT_NEXT, bool LAST>
__device__ __forceinline__ void run_layer(char* smem, uint32_t sm_base,
                                          const __nv_bfloat16* gW,
                                          const __nv_bfloat16* gW_next,
                                          const float* __restrict__ bias,
                                          float* __restrict__ out_g,
                                          int nbase, int n)
{
    const int lane = threadIdx.x & 31, wid = threadIdx.x >> 5;
    const int wm = wid >> 2, wn = wid & 3;    // 2 x 4 warp grid
    constexpr int NT = OUT / 32;              // n8-tiles per warp (8 or 4)
    const int warpn = wn * (NT * 8);          // warp n-col base

    const int arow = wm * 32 + (lane & 15);
    const int acol = (lane >> 4) * 8;
    const int b_noff = ((lane >> 4) & 1) * 8 + (lane & 7);
    const int b_kby  = ((lane >> 3) & 1) * 16;

    float acc[2][NT][4];
    #pragma unroll
    for (int mt = 0; mt < 2; ++mt)
        #pragma unroll
        for (int nt = 0; nt < NT; ++nt)
            #pragma unroll
            for (int c = 0; c < 4; ++c) acc[mt][nt][c] = 0.f;

    const uint32_t bb0 = sm_base + B_OFF + (uint32_t)(warpn + b_noff) * 80 + b_kby;

    for (int kc = 0; kc < 8; ++kc) {
        // ---- hi tile (2kc) in buffer 0 ----
        asm volatile("cp.async.wait_group 1;");
        __syncthreads();
        #pragma unroll
        for (int ks = 0; ks < 2; ++ks) {
            const int k0 = kc * 32 + ks * 16;
            uint32_t ahi[2][4], alo[2][4];
            #pragma unroll
            for (int mt = 0; mt < 2; ++mt) {
                uint32_t aaddr = sm_base +
                    (uint32_t)(((arow + mt * 16) * AS + k0 + acol) * 2);
                ldm_x4(ahi[mt], aaddr + A_HI_OFF);
                ldm_x4(alo[mt], aaddr + A_LO_OFF);
            }
            #pragma unroll
            for (int np = 0; np < NT / 2; ++np) {
                uint32_t bh[4];
                ldm_x4(bh, bb0 + (uint32_t)(np * 16 * 80 + ks * 32));
                #pragma unroll
                for (int q = 0; q < 2; ++q)
                    #pragma unroll
                    for (int mt = 0; mt < 2; ++mt)
                        mma_bf16(acc[mt][np * 2 + q], ahi[mt],
                                 bh[2 * q], bh[2 * q + 1]);
                #pragma unroll
                for (int q = 0; q < 2; ++q)
                    #pragma unroll
                    for (int mt = 0; mt < 2; ++mt)
                        mma_bf16(acc[mt][np * 2 + q], alo[mt],
                                 bh[2 * q], bh[2 * q + 1]);
            }
        }
        __syncthreads();
        // commit tile 2kc+2 into buffer 0
        {
            int idx = 2 * kc + 2;
            if (idx < 16)
                load_tile<OUT>(sm_base + B_OFF,
                               gW + (size_t)(idx >> 1) * 2 * OUT * 32
                                  + (size_t)(idx & 1) * OUT * 32);
            else if (!LAST)
                load_tile<OUT_NEXT>(sm_base + B_OFF,
                                    gW_next + (size_t)(idx - 16) * OUT_NEXT * 32);
        }
        // ---- lo tile (2kc+1) in buffer 1 ----
        if (LAST && kc == 7) asm volatile("cp.async.wait_group 0;");
        else                 asm volatile("cp.async.wait_group 1;");
        __syncthreads();
        #pragma unroll
        for (int ks = 0; ks < 2; ++ks) {
            const int k0 = kc * 32 + ks * 16;
            uint32_t ahi[2][4];
            #pragma unroll
            for (int mt = 0; mt < 2; ++mt) {
                uint32_t aaddr = sm_base +
                    (uint32_t)(((arow + mt * 16) * AS + k0 + acol) * 2);
                ldm_x4(ahi[mt], aaddr + A_HI_OFF);
            }
            #pragma unroll
            for (int np = 0; np < NT / 2; ++np) {
                uint32_t bl[4];
                ldm_x4(bl, bb0 + BUFSZ + (uint32_t)(np * 16 * 80 + ks * 32));
                #pragma unroll
                for (int q = 0; q < 2; ++q)
                    #pragma unroll
                    for (int mt = 0; mt < 2; ++mt)
                        mma_bf16(acc[mt][np * 2 + q], ahi[mt],
                                 bl[2 * q], bl[2 * q + 1]);
            }
        }
        __syncthreads();
        // commit tile 2kc+3 into buffer 1
        {
            int idx = 2 * kc + 3;
            if (idx < 16)
                load_tile<OUT>(sm_base + B_OFF + BUFSZ,
                               gW + (size_t)(idx >> 1) * 2 * OUT * 32
                                  + (size_t)(idx & 1) * OUT * 32);
            else if (!LAST)
                load_tile<OUT_NEXT>(sm_base + B_OFF + BUFSZ,
                                    gW_next + (size_t)(idx - 16) * OUT_NEXT * 32);
        }
    }

    // ---- epilogue ----
    float2 bv[NT];
    #pragma unroll
    for (int nt = 0; nt < NT; ++nt)
        bv[nt] = __ldg((const float2*)(bias + warpn + nt * 8 + (lane & 3) * 2));

    #pragma unroll
    for (int mt = 0; mt < 2; ++mt) {
        int row0 = wm * 32 + mt * 16 + (lane >> 2);
        #pragma unroll
        for (int nt = 0; nt < NT; ++nt) {
            int col = warpn + nt * 8 + (lane & 3) * 2;
            float v0 = acc[mt][nt][0] + bv[nt].x, v1 = acc[mt][nt][1] + bv[nt].y;
            float v2 = acc[mt][nt][2] + bv[nt].x, v3 = acc[mt][nt][3] + bv[nt].y;
            if (LAST) {
                int n0 = nbase + row0, n1 = n0 + 8;
                if (n0 < n) {
                    float2 t = {v0, v1};
                    *(float2*)(out_g + (size_t)n0 * OUT + col) = t;
                }
                if (n1 < n) {
                    float2 t = {v2, v3};
                    *(float2*)(out_g + (size_t)n1 * OUT + col) = t;
                }
            } else {
                store_split(smem, row0,     col, fmaxf(v0, 0.f), fmaxf(v1, 0.f));
                store_split(smem, row0 + 8, col, fmaxf(v2, 0.f), fmaxf(v3, 0.f));
            }
        }
    }
    if (!LAST) __syncthreads();
}

// ---------------- kernel 3: HMMA MLP (M=64, 2 CTAs/SM) ---------------------
__global__ void __launch_bounds__(TPB)
mlp_mma_kernel(const float* __restrict__ x,
               const float* __restrict__ b1, const float* __restrict__ b2,
               const float* __restrict__ b3,
               float* __restrict__ out, int n)
{
    extern __shared__ char smem[];
    const uint32_t sm_base = smem_u32(smem);
    const int tid = threadIdx.x;
    const int nbase = blockIdx.x * MROWS;

    // prologue: tiles 0 (hi) and 1 (lo) of layer-1 kc=0
    load_tile<256>(sm_base + B_OFF,         g_Wt);
    load_tile<256>(sm_base + B_OFF + BUFSZ, g_Wt + 256 * 32);

    // Build A = concat(x, scatter-mean) as bf16 hi/lo, padded rows.
    {
        int m = tid >> 2, q = tid & 3;        // 4 threads per node row
        int node = nbase + m;
        bool valid = node < n;
        const float4* src = (q < 2)
            ? (const float4*)x      + (size_t)node * 32 + q * 16
            : (const float4*)g_sums + (size_t)node * 32 + (q - 2) * 16;
        float inv = 1.f;
        if (valid && q >= 2) inv = 1.f / fmaxf(g_counts[node], 1.f);
        #pragma unroll 4
        for (int f = 0; f < 16; ++f) {
            float4 v = make_float4(0.f, 0.f, 0.f, 0.f);
            if (valid) {
                v = __ldg(src + f);
                if (q >= 2) { v.x *= inv; v.y *= inv; v.z *= inv; v.w *= inv; }
            }
            int col = q * 64 + f * 4;
            store_split(smem, m, col,     v.x, v.y);
            store_split(smem, m, col + 2, v.z, v.w);
        }
    }
    __syncthreads();

    run_layer<256, 256, false>(smem, sm_base, g_Wt,          g_Wt + 131072,
                               b1, nullptr, nbase, n);
    run_layer<256, 128, false>(smem, sm_base, g_Wt + 131072, g_Wt + 262144,
                               b2, nullptr, nbase, n);
    run_layer<128, 128, true >(smem, sm_base, g_Wt + 262144, nullptr,
                               b3, out, nbase, n);
}

// ---------------- launcher --------------------------------------------------
extern "C" void kernel_launch(void* const* d_in, const int* in_sizes, int n_in,
                              void* d_out, int out_size)
{
    const float* x          = (const float*)d_in[0];
    const int*   edge_index = (const int*)  d_in[1];
    const float* edge_attr  = (const float*)d_in[2];
    const float* W1 = (const float*)d_in[3];
    const float* b1 = (const float*)d_in[4];
    const float* W2 = (const float*)d_in[5];
    const float* b2 = (const float*)d_in[6];
    const float* W3 = (const float*)d_in[7];
    const float* b3 = (const float*)d_in[8];
    float* out = (float*)d_out;

    int n_nodes = in_sizes[0] / 128;
    int n_edges = in_sizes[1] / 2;
    const int* col = edge_index + n_edges;

    cudaFuncSetAttribute(mlp_mma_kernel,
                         cudaFuncAttributeMaxDynamicSharedMemorySize, SMEM_TOTAL);

    // 1) zero accumulators
    {
        int n4 = n_nodes * 32;
        zero_kernel<<<(n4 + 255) / 256, 256>>>(n_nodes);
    }
    // 2) prep weights (bf16 hi/lo, transposed + k-chunked, coalesced)
    prep_kernel<<<80, 256>>>(W1, W2, W3);
    // 3) scatter-add (one warp per edge, vector atomics)
    {
        long long total = (long long)n_edges * 32;
        scatter_kernel<<<(int)((total + 255) / 256), 256>>>(edge_attr, col, n_edges);
    }
    // 4) HMMA MLP (M=64 CTAs, 2 per SM)
    {
        int blocks = (n_nodes + MROWS - 1) / MROWS;
        mlp_mma_kernel<<<blocks, TPB, SMEM_TOTAL>>>(x, b1, b2, b3, out, n_nodes);
    }
}

// round 13
// speedup vs baseline: 1.2452x; 1.0410x over previous
#include <cuda_runtime.h>
#include <cuda_fp16.h>
#include <cstdint>

// ---------------- scratch (device globals: no allocation allowed) ----------
#define MAX_NODES 100000
__device__ __align__(16) float g_sums[(size_t)MAX_NODES * 128];
__device__ float g_counts[MAX_NODES];
// fp16 weights, transposed + k-chunked: per layer [kc][n][32k]
// L1 @0 (65536), L2 @65536, L3 @131072 ; total 163840 halves
__device__ __align__(16) __half g_Wt[163840];

// ---------------- helpers ---------------------------------------------------
__device__ __forceinline__ uint32_t smem_u32(const void* p) {
    uint32_t a;
    asm("{ .reg .u64 t; cvta.to.shared.u64 t, %1; cvt.u32.u64 %0, t; }"
        : "=r"(a) : "l"(p));
    return a;
}
__device__ __forceinline__ void cp_async16(uint32_t saddr, const void* g) {
    asm volatile("cp.async.cg.shared.global [%0], [%1], 16;" :: "r"(saddr), "l"(g));
}
__device__ __forceinline__ void ldm_x4(uint32_t* r, uint32_t addr) {
    asm volatile("ldmatrix.sync.aligned.m8n8.x4.shared.b16 {%0,%1,%2,%3}, [%4];"
        : "=r"(r[0]), "=r"(r[1]), "=r"(r[2]), "=r"(r[3]) : "r"(addr));
}
__device__ __forceinline__ void mma_fp16(float* c, const uint32_t* a,
                                         uint32_t b0, uint32_t b1) {
    asm volatile("mma.sync.aligned.m16n8k16.row.col.f32.f16.f16.f32 "
        "{%0,%1,%2,%3}, {%4,%5,%6,%7}, {%8,%9}, {%0,%1,%2,%3};"
        : "+f"(c[0]), "+f"(c[1]), "+f"(c[2]), "+f"(c[3])
        : "r"(a[0]), "r"(a[1]), "r"(a[2]), "r"(a[3]), "r"(b0), "r"(b1));
}
__device__ __forceinline__ uint32_t pack_h(__half a, __half b) {
    return (uint32_t)__half_as_ushort(a) | ((uint32_t)__half_as_ushort(b) << 16);
}

// smem layout (bytes) — M=64 CTA, 2 CTAs/SM
constexpr int TPB      = 256;                 // 8 warps per CTA
constexpr int MROWS    = 64;                  // nodes per CTA
constexpr int AS       = 264;                 // A row stride (elements)
constexpr int A_HI_OFF = 0;                   // 64*264*2 = 33792
constexpr int A_LO_OFF = 33792;
constexpr int B_OFF    = 67584;
constexpr int BUFSZ    = 20480;               // one fp16 B tile (OUT=256: 256*80)
constexpr int SMEM_TOTAL = B_OFF + 2 * BUFSZ; // 108544 -> 2 CTAs/SM

// activations stored as exact fp16 hi+lo pair (a = a_hi + a_lo to 2^-22)
__device__ __forceinline__ void store_split(char* smem, int row, int col,
                                            float v0, float v1) {
    __half h0 = __float2half_rn(v0), h1 = __float2half_rn(v1);
    __half l0 = __float2half_rn(v0 - __half2float(h0));
    __half l1 = __float2half_rn(v1 - __half2float(h1));
    uint32_t off = (uint32_t)(row * AS + col) * 2;
    *(uint32_t*)(smem + A_HI_OFF + off) = pack_h(h0, h1);
    *(uint32_t*)(smem + A_LO_OFF + off) = pack_h(l0, l1);
}

// ---------------- kernel 1: zero the scatter accumulators ------------------
__global__ void zero_kernel(int n_nodes) {
    int i = blockIdx.x * blockDim.x + threadIdx.x;
    int n4 = n_nodes * 32;
    if (i < n4) ((float4*)g_sums)[i] = make_float4(0.f, 0.f, 0.f, 0.f);
    if (i < n_nodes) g_counts[i] = 0.f;
}

// ---------------- kernel 2: scatter-add (vector atomics) -------------------
__global__ void scatter_kernel(const float* __restrict__ edge_attr,
                               const int*   __restrict__ col,
                               int n_edges) {
    int t = blockIdx.x * blockDim.x + threadIdx.x;
    int e = t >> 5;
    int lane = t & 31;
    if (e >= n_edges) return;
    int c = __ldg(col + e);
    float4 v = ((const float4*)edge_attr)[(size_t)e * 32 + lane];
    float* dst = g_sums + (size_t)c * 128 + lane * 4;
    asm volatile("red.global.add.v4.f32 [%0], {%1,%2,%3,%4};"
                 :: "l"(dst), "f"(v.x), "f"(v.y), "f"(v.z), "f"(v.w) : "memory");
    if (lane == 0) atomicAdd(g_counts + c, 1.0f);
}

// ---------------- kernel: prep weights -> g_Wt (fp16, coalesced) -----------
// Layout per layer: [kc][n][32k] fp16, n-major rows (W^T).
__global__ void prep_kernel(const float* __restrict__ W1,
                            const float* __restrict__ W2,
                            const float* __restrict__ W3) {
    __shared__ float tile[32][65];
    int b = blockIdx.x;
    const float* W; int base, OUT, t;
    if (b < 32)      { W = W1; base = 0;      OUT = 256; t = b; }
    else if (b < 64) { W = W2; base = 65536;  OUT = 256; t = b - 32; }
    else             { W = W3; base = 131072; OUT = 128; t = b - 64; }
    int nbt = OUT / 64;
    int kc = t / nbt, nb = t % nbt;
    int tid = threadIdx.x;
    #pragma unroll
    for (int i = 0; i < 8; ++i) {
        int idx = tid + i * 256;
        int kr = idx >> 6, nc = idx & 63;
        tile[kr][nc] = __ldg(W + (size_t)(kc * 32 + kr) * OUT + nb * 64 + nc);
    }
    __syncthreads();
    int nn = tid >> 2, kq = tid & 3;          // thread: node row nn, 8 k vals
    uint4 vh;
    uint32_t* ph = (uint32_t*)&vh;
    #pragma unroll
    for (int j = 0; j < 4; ++j) {
        float w0 = tile[kq * 8 + 2 * j][nn];
        float w1 = tile[kq * 8 + 2 * j + 1][nn];
        ph[j] = pack_h(__float2half_rn(w0), __float2half_rn(w1));
    }
    size_t o = (size_t)base + ((size_t)kc * OUT + nb * 64 + nn) * 32 + kq * 8;
    *(uint4*)(g_Wt + o) = vh;
}

// ---------------- B tile loader (one kc: OUT rows x 32 k fp16) -------------
template<int OUT>
__device__ __forceinline__ void load_tile(uint32_t bdst, const __half* gsrc) {
    constexpr int UNITS = OUT * 4;            // 16B units (64B data/row)
    #pragma unroll
    for (int u = threadIdx.x; u < UNITS; u += TPB) {
        int nn = u >> 2, part = u & 3;
        cp_async16(bdst + nn * 80 + part * 16, (const char*)gsrc + (size_t)u * 16);
    }
    asm volatile("cp.async.commit_group;");
}

// ---------------- one MLP layer: fp16 2-pass HMMA ---------------------------
// Warp grid 2(m) x 4(n). 8 tiles/layer (one per kc), tile kc in buffer kc&1.
// Entry invariant: this layer's tiles 0,1 committed. After computing tile kc,
// tile kc+2 (or next layer's tile kc+2-8) is committed into the freed buffer.
template<int OUT, int OUT_NEXT, bool LAST>
__device__ __forceinline__ void run_layer(char* smem, uint32_t sm_base,
                                          const __half* gW,
                                          const __half* gW_next,
                                          const float* __restrict__ bias,
                                          float* __restrict__ out_g,
                                          int nbase, int n)
{
    const int lane = threadIdx.x & 31, wid = threadIdx.x >> 5;
    const int wm = wid >> 2, wn = wid & 3;    // 2 x 4 warp grid
    constexpr int NT = OUT / 32;              // n8-tiles per warp (8 or 4)
    const int warpn = wn * (NT * 8);

    const int arow = wm * 32 + (lane & 15);
    const int acol = (lane >> 4) * 8;
    const int b_noff = ((lane >> 4) & 1) * 8 + (lane & 7);
    const int b_kby  = ((lane >> 3) & 1) * 16;

    float acc[2][NT][4];
    #pragma unroll
    for (int mt = 0; mt < 2; ++mt)
        #pragma unroll
        for (int nt = 0; nt < NT; ++nt)
            #pragma unroll
            for (int c = 0; c < 4; ++c) acc[mt][nt][c] = 0.f;

    const uint32_t bb0 = sm_base + B_OFF + (uint32_t)(warpn + b_noff) * 80 + b_kby;

    for (int kc = 0; kc < 8; ++kc) {
        if (LAST && kc == 7) asm volatile("cp.async.wait_group 0;");
        else                 asm volatile("cp.async.wait_group 1;");
        __syncthreads();                      // tile kc visible

        const uint32_t bbuf = bb0 + (uint32_t)((kc & 1) * BUFSZ);
        #pragma unroll
        for (int ks = 0; ks < 2; ++ks) {
            const int k0 = kc * 32 + ks * 16;
            uint32_t ahi[2][4], alo[2][4];
            #pragma unroll
            for (int mt = 0; mt < 2; ++mt) {
                uint32_t aaddr = sm_base +
                    (uint32_t)(((arow + mt * 16) * AS + k0 + acol) * 2);
                ldm_x4(ahi[mt], aaddr + A_HI_OFF);
                ldm_x4(alo[mt], aaddr + A_LO_OFF);
            }
            #pragma unroll
            for (int np = 0; np < NT / 2; ++np) {
                uint32_t bv[4];
                ldm_x4(bv, bbuf + (uint32_t)(np * 16 * 80 + ks * 32));
                // pass 1: a_hi * b
                #pragma unroll
                for (int q = 0; q < 2; ++q)
                    #pragma unroll
                    for (int mt = 0; mt < 2; ++mt)
                        mma_fp16(acc[mt][np * 2 + q], ahi[mt],
                                 bv[2 * q], bv[2 * q + 1]);
                // pass 2: a_lo * b  (a_hi+a_lo == a exactly)
                #pragma unroll
                for (int q = 0; q < 2; ++q)
                    #pragma unroll
                    for (int mt = 0; mt < 2; ++mt)
                        mma_fp16(acc[mt][np * 2 + q], alo[mt],
                                 bv[2 * q], bv[2 * q + 1]);
            }
        }
        __syncthreads();                      // reads of this buffer done

        // commit tile kc+2 into the freed buffer
        int idx = kc + 2;
        if (idx < 8)
            load_tile<OUT>(sm_base + B_OFF + (idx & 1) * BUFSZ,
                           gW + (size_t)idx * OUT * 32);
        else if (!LAST)
            load_tile<OUT_NEXT>(sm_base + B_OFF + (idx & 1) * BUFSZ,
                                gW_next + (size_t)(idx - 8) * OUT_NEXT * 32);
    }

    // ---- epilogue ----
    float2 bv2[NT];
    #pragma unroll
    for (int nt = 0; nt < NT; ++nt)
        bv2[nt] = __ldg((const float2*)(bias + warpn + nt * 8 + (lane & 3) * 2));

    #pragma unroll
    for (int mt = 0; mt < 2; ++mt) {
        int row0 = wm * 32 + mt * 16 + (lane >> 2);
        #pragma unroll
        for (int nt = 0; nt < NT; ++nt) {
            int col = warpn + nt * 8 + (lane & 3) * 2;
            float v0 = acc[mt][nt][0] + bv2[nt].x, v1 = acc[mt][nt][1] + bv2[nt].y;
            float v2 = acc[mt][nt][2] + bv2[nt].x, v3 = acc[mt][nt][3] + bv2[nt].y;
            if (LAST) {
                int n0 = nbase + row0, n1 = n0 + 8;
                if (n0 < n) {
                    float2 t = {v0, v1};
                    *(float2*)(out_g + (size_t)n0 * OUT + col) = t;
                }
                if (n1 < n) {
                    float2 t = {v2, v3};
                    *(float2*)(out_g + (size_t)n1 * OUT + col) = t;
                }
            } else {
                store_split(smem, row0,     col, fmaxf(v0, 0.f), fmaxf(v1, 0.f));
                store_split(smem, row0 + 8, col, fmaxf(v2, 0.f), fmaxf(v3, 0.f));
            }
        }
    }
    if (!LAST) __syncthreads();
}

// ---------------- kernel 3: HMMA MLP (M=64, 2 CTAs/SM, fp16 2-pass) --------
__global__ void __launch_bounds__(TPB)
mlp_mma_kernel(const float* __restrict__ x,
               const float* __restrict__ b1, const float* __restrict__ b2,
               const float* __restrict__ b3,
               float* __restrict__ out, int n)
{
    extern __shared__ char smem[];
    const uint32_t sm_base = smem_u32(smem);
    const int tid = threadIdx.x;
    const int nbase = blockIdx.x * MROWS;

    // prologue: tiles 0 and 1 of layer 1
    load_tile<256>(sm_base + B_OFF,         g_Wt);
    load_tile<256>(sm_base + B_OFF + BUFSZ, g_Wt + 256 * 32);

    // Build A = concat(x, scatter-mean) as fp16 hi/lo, padded rows.
    {
        int m = tid >> 2, q = tid & 3;        // 4 threads per node row
        int node = nbase + m;
        bool valid = node < n;
        const float4* src = (q < 2)
            ? (const float4*)x      + (size_t)node * 32 + q * 16
            : (const float4*)g_sums + (size_t)node * 32 + (q - 2) * 16;
        float inv = 1.f;
        if (valid && q >= 2) inv = 1.f / fmaxf(g_counts[node], 1.f);
        #pragma unroll 4
        for (int f = 0; f < 16; ++f) {
            float4 v = make_float4(0.f, 0.f, 0.f, 0.f);
            if (valid) {
                v = __ldg(src + f);
                if (q >= 2) { v.x *= inv; v.y *= inv; v.z *= inv; v.w *= inv; }
            }
            int col = q * 64 + f * 4;
            store_split(smem, m, col,     v.x, v.y);
            store_split(smem, m, col + 2, v.z, v.w);
        }
    }
    __syncthreads();

    run_layer<256, 256, false>(smem, sm_base, g_Wt,          g_Wt + 65536,
                               b1, nullptr, nbase, n);
    run_layer<256, 128, false>(smem, sm_base, g_Wt + 65536,  g_Wt + 131072,
                               b2, nullptr, nbase, n);
    run_layer<128, 128, true >(smem, sm_base, g_Wt + 131072, nullptr,
                               b3, out, nbase, n);
}

// ---------------- launcher --------------------------------------------------
extern "C" void kernel_launch(void* const* d_in, const int* in_sizes, int n_in,
                              void* d_out, int out_size)
{
    const float* x          = (const float*)d_in[0];
    const int*   edge_index = (const int*)  d_in[1];
    const float* edge_attr  = (const float*)d_in[2];
    const float* W1 = (const float*)d_in[3];
    const float* b1 = (const float*)d_in[4];
    const float* W2 = (const float*)d_in[5];
    const float* b2 = (const float*)d_in[6];
    const float* W3 = (const float*)d_in[7];
    const float* b3 = (const float*)d_in[8];
    float* out = (float*)d_out;

    int n_nodes = in_sizes[0] / 128;
    int n_edges = in_sizes[1] / 2;
    const int* col = edge_index + n_edges;

    cudaFuncSetAttribute(mlp_mma_kernel,
                         cudaFuncAttributeMaxDynamicSharedMemorySize, SMEM_TOTAL);

    // 1) zero accumulators
    {
        int n4 = n_nodes * 32;
        zero_kernel<<<(n4 + 255) / 256, 256>>>(n_nodes);
    }
    // 2) prep weights (fp16, transposed + k-chunked, coalesced)
    prep_kernel<<<80, 256>>>(W1, W2, W3);
    // 3) scatter-add (one warp per edge, vector atomics)
    {
        long long total = (long long)n_edges * 32;
        scatter_kernel<<<(int)((total + 255) / 256), 256>>>(edge_attr, col, n_edges);
    }
    // 4) HMMA MLP (M=64 CTAs, 2 per SM, fp16 2-pass)
    {
        int blocks = (n_nodes + MROWS - 1) / MROWS;
        mlp_mma_kernel<<<blocks, TPB, SMEM_TOTAL>>>(x, b1, b2, b3, out, n_nodes);
    }
}